// round 3
// baseline (speedup 1.0000x reference)
#include <cuda_runtime.h>
#include <cuda_bf16.h>

#define RGRID 128
#define NSTEPS 128
#define NCH 28

__device__ __forceinline__ float gsum8(float v, unsigned m) {
    v += __shfl_xor_sync(m, v, 1);
    v += __shfl_xor_sync(m, v, 2);
    v += __shfl_xor_sync(m, v, 4);
    return v;
}

__global__ void __launch_bounds__(256, 4) octree_render_kernel(
    const float* __restrict__ rays_o,
    const float* __restrict__ rays_d,
    const float* __restrict__ grid,
    const float* __restrict__ scaling,
    const float* __restrict__ offset,
    float* __restrict__ out,
    int N)
{
    int tid  = blockIdx.x * blockDim.x + threadIdx.x;
    int ray  = tid >> 3;          // 8 lanes per ray
    int c    = tid & 7;           // corner id: bit2=dx, bit1=dy, bit0=dz
    if (ray >= N) return;

    int lane = threadIdx.x & 31;
    unsigned gmask = 0xFFu << (lane & 24);   // this 8-lane group's mask

    float rox = rays_o[3*ray+0], roy = rays_o[3*ray+1], roz = rays_o[3*ray+2];
    float rdx = rays_d[3*ray+0], rdy = rays_d[3*ray+1], rdz = rays_d[3*ray+2];

    float inv_n = rsqrtf(rdx*rdx + rdy*rdy + rdz*rdz);
    float ux = rdx*inv_n, uy = rdy*inv_n, uz = rdz*inv_n;

    float sx = scaling[0], sy = scaling[1], sz = scaling[2];
    float fx = offset[0],  fy = offset[1],  fz = offset[2];

    float ox = rox*sx + fx, oy = roy*sy + fy, oz = roz*sz + fz;
    float dx = ux*sx, dy = uy*sy, dz = uz*sz;

    float dlen = sqrtf(dx*dx + dy*dy + dz*dz);
    float delta_scale = 1.0f/dlen;

    float ivx = 1.0f/((fabsf(dx) > 1e-9f) ? dx : 1e-9f);
    float ivy = 1.0f/((fabsf(dy) > 1e-9f) ? dy : 1e-9f);
    float ivz = 1.0f/((fabsf(dz) > 1e-9f) ? dz : 1e-9f);

    float t1x = (0.0f - ox)*ivx, t2x = (1.0f - ox)*ivx;
    float t1y = (0.0f - oy)*ivy, t2y = (1.0f - oy)*ivy;
    float t1z = (0.0f - oz)*ivz, t2z = (1.0f - oz)*ivz;

    float tlo = fmaxf(fmaxf(fminf(t1x,t2x), fminf(t1y,t2y)), fminf(t1z,t2z));
    float thi = fminf(fminf(fmaxf(t1x,t2x), fmaxf(t1y,t2y)), fmaxf(t1z,t2z));
    float tmin = fmaxf(tlo, 0.0f);

    bool alive = (thi > tmin);

    float T = 1.0f, cr = 0.0f, cg = 0.0f, cb = 0.0f;

    if (alive) {
        float dt   = (thi - tmin) * (1.0f/(float)NSTEPS);
        float dtds = dt * delta_scale;

        // SH degree-2 basis
        const float C0 = 0.28209479177387814f;
        const float C1 = 0.4886025119029199f;
        float b0 = C0;
        float b1 = -C1*uy;
        float b2 =  C1*uz;
        float b3 = -C1*ux;
        float b4 =  1.0925484305920792f*ux*uy;
        float b5 = -1.0925484305920792f*uy*uz;
        float b6 =  0.31539156525252005f*(2.0f*uz*uz - ux*ux - uy*uy);
        float b7 = -1.0925484305920792f*ux*uz;
        float b8 =  0.5462742152960396f*(ux*ux - uy*uy);

        const int SY = RGRID*NCH;
        const int SX = RGRID*RGRID*NCH;
        int cx = (c >> 2) & 1, cy = (c >> 1) & 1, cz = c & 1;
        int coff = cx*SX + cy*SY + cz*NCH;

        // pre-scaled ray constants: pos_grid = fma(t, dR, oR)
        float oxR = fmaf(ox, (float)RGRID, -0.5f);
        float oyR = fmaf(oy, (float)RGRID, -0.5f);
        float ozR = fmaf(oz, (float)RGRID, -0.5f);
        float dxR = dx*(float)RGRID, dyR = dy*(float)RGRID, dzR = dz*(float)RGRID;

        // sample prep: base offset + this corner's trilerp weight
        auto prep = [&](int s, int& bse, float& wc) {
            float t  = tmin + ((float)s + 0.5f)*dt;
            float px = fminf(fmaxf(fmaf(t, dxR, oxR), 0.0f), 126.9999f);
            float py = fminf(fmaxf(fmaf(t, dyR, oyR), 0.0f), 126.9999f);
            float pz = fminf(fmaxf(fmaf(t, dzR, ozR), 0.0f), 126.9999f);
            float gx = floorf(px), gy = floorf(py), gz = floorf(pz);
            int ix = (int)gx, iy = (int)gy, iz = (int)gz;
            float wxx = px - gx, wyy = py - gy, wzz = pz - gz;
            bse = ((ix*RGRID + iy)*RGRID + iz)*NCH + coff;
            wc  = (cx ? wxx : 1.0f - wxx)
                * (cy ? wyy : 1.0f - wyy)
                * (cz ? wzz : 1.0f - wzz);
        };

        // depth-2 pipeline: sigma for step s is loaded 2 iterations ahead
        int   bs0, bs1;
        float wc0, wc1, sp0, sp1;
        prep(0, bs0, wc0); sp0 = wc0 * __ldg(grid + bs0 + (NCH-1));
        prep(1, bs1, wc1); sp1 = wc1 * __ldg(grid + bs1 + (NCH-1));

        for (int s = 0; s < NSTEPS; ++s) {
            float sg = gsum8(sp0, gmask);

            // prefetch sigma for s+2 (clamped; duplicate load at tail is harmless)
            int sp = s + 2; if (sp >= NSTEPS) sp = NSTEPS - 1;
            int bn; float wn;
            prep(sp, bn, wn);
            float spn = wn * __ldg(grid + bn + (NCH-1));

            if (sg > 0.0f) {   // group-uniform: relu(trilerp sigma) == 0 otherwise
                const float4* p = reinterpret_cast<const float4*>(grid + bs0);
                float4 v0 = __ldg(p+0);
                float4 v1 = __ldg(p+1);
                float4 v2 = __ldg(p+2);
                float4 v3 = __ldg(p+3);
                float4 v4 = __ldg(p+4);
                float4 v5 = __ldg(p+5);
                float4 v6 = __ldg(p+6);

                float d0 = b0*v0.x + b1*v0.y + b2*v0.z + b3*v0.w
                         + b4*v1.x + b5*v1.y + b6*v1.z + b7*v1.w + b8*v2.x;
                float d1 = b0*v2.y + b1*v2.z + b2*v2.w
                         + b3*v3.x + b4*v3.y + b5*v3.z + b6*v3.w
                         + b7*v4.x + b8*v4.y;
                float d2 = b0*v4.z + b1*v4.w
                         + b2*v5.x + b3*v5.y + b4*v5.z + b5*v5.w
                         + b6*v6.x + b7*v6.y + b8*v6.z;

                float a0 = gsum8(wc0 * d0, gmask);
                float a1 = gsum8(wc0 * d1, gmask);
                float a2 = gsum8(wc0 * d2, gmask);

                float alpha = 1.0f - __expf(-sg*dtds);
                float s0 = 1.0f/(1.0f + __expf(-a0));
                float s1 = 1.0f/(1.0f + __expf(-a1));
                float s2 = 1.0f/(1.0f + __expf(-a2));

                float Ta = T*alpha;
                cr = fmaf(Ta, s0, cr);
                cg = fmaf(Ta, s1, cg);
                cb = fmaf(Ta, s2, cb);
                T  = T*(1.0f - alpha);
                if (T < 1e-4f) break;   // bounded 1e-4 abs error; group-uniform
            }

            bs0 = bs1; wc0 = wc1; sp0 = sp1;
            bs1 = bn;  wc1 = wn;  sp1 = spn;
        }
    }

    if (c == 0) {
        out[3*ray+0] = fmaf(T, 1.0f, cr);
        out[3*ray+1] = fmaf(T, 1.0f, cg);
        out[3*ray+2] = fmaf(T, 1.0f, cb);
    }
}

extern "C" void kernel_launch(void* const* d_in, const int* in_sizes, int n_in,
                              void* d_out, int out_size) {
    const float* rays_o  = (const float*)d_in[0];
    const float* rays_d  = (const float*)d_in[1];
    const float* grid    = (const float*)d_in[2];
    const float* scaling = (const float*)d_in[3];
    const float* offset  = (const float*)d_in[4];
    float* out = (float*)d_out;

    int N = in_sizes[0] / 3;                 // rays
    int threads_total = N * 8;               // 8 lanes per ray
    int block = 256;
    int blocks = (threads_total + block - 1) / block;
    octree_render_kernel<<<blocks, block>>>(rays_o, rays_d, grid, scaling, offset, out, N);
}

// round 4
// speedup vs baseline: 1.0952x; 1.0952x over previous
#include <cuda_runtime.h>
#include <cuda_fp16.h>

#define RGRID 128
#define NSTEPS 128
#define NCH 28
#define NV (RGRID*RGRID*RGRID)

// fp16 repacked grid: 32 halves (64 B) per voxel, 64-B aligned.
// [0..26] = SH coeffs, [27] = sigma, [28..31] = pad.
__device__ __align__(16) __half g_grid16[(size_t)NV * 32];

__device__ __forceinline__ unsigned pk(float a, float b) {
    __half2 h = __floats2half2_rn(a, b);
    return *reinterpret_cast<unsigned*>(&h);
}
__device__ __forceinline__ float2 up(unsigned u) {
    __half2 h = *reinterpret_cast<__half2*>(&u);
    return __half22float2(h);
}

__global__ void __launch_bounds__(256) convert_kernel(const float* __restrict__ grid) {
    int v = blockIdx.x * blockDim.x + threadIdx.x;
    if (v >= NV) return;
    const float4* src = reinterpret_cast<const float4*>(grid + (size_t)v * NCH);
    float4 f0 = __ldg(src+0), f1 = __ldg(src+1), f2 = __ldg(src+2), f3 = __ldg(src+3);
    float4 f4 = __ldg(src+4), f5 = __ldg(src+5), f6 = __ldg(src+6);

    uint4 q0 = make_uint4(pk(f0.x,f0.y), pk(f0.z,f0.w), pk(f1.x,f1.y), pk(f1.z,f1.w));
    uint4 q1 = make_uint4(pk(f2.x,f2.y), pk(f2.z,f2.w), pk(f3.x,f3.y), pk(f3.z,f3.w));
    uint4 q2 = make_uint4(pk(f4.x,f4.y), pk(f4.z,f4.w), pk(f5.x,f5.y), pk(f5.z,f5.w));
    uint2 q3 = make_uint2(pk(f6.x,f6.y), pk(f6.z,f6.w));

    uint4* dst = reinterpret_cast<uint4*>(g_grid16 + (size_t)v * 32);
    dst[0] = q0; dst[1] = q1; dst[2] = q2;
    reinterpret_cast<uint2*>(dst + 3)[0] = q3;
}

__device__ __forceinline__ float gsum8(float v, unsigned m) {
    v += __shfl_xor_sync(m, v, 1);
    v += __shfl_xor_sync(m, v, 2);
    v += __shfl_xor_sync(m, v, 4);
    return v;
}

__global__ void __launch_bounds__(256, 4) octree_render_kernel(
    const float* __restrict__ rays_o,
    const float* __restrict__ rays_d,
    const float* __restrict__ scaling,
    const float* __restrict__ offset,
    float* __restrict__ out,
    int N)
{
    int tid  = blockIdx.x * blockDim.x + threadIdx.x;
    int ray  = tid >> 3;          // 8 lanes per ray
    int c    = tid & 7;           // corner id: bit2=dx, bit1=dy, bit0=dz
    if (ray >= N) return;

    int lane = threadIdx.x & 31;
    unsigned gmask = 0xFFu << (lane & 24);

    float rox = rays_o[3*ray+0], roy = rays_o[3*ray+1], roz = rays_o[3*ray+2];
    float rdx = rays_d[3*ray+0], rdy = rays_d[3*ray+1], rdz = rays_d[3*ray+2];

    float inv_n = rsqrtf(rdx*rdx + rdy*rdy + rdz*rdz);
    float ux = rdx*inv_n, uy = rdy*inv_n, uz = rdz*inv_n;

    float sx = scaling[0], sy = scaling[1], sz = scaling[2];
    float fx = offset[0],  fy = offset[1],  fz = offset[2];

    float ox = rox*sx + fx, oy = roy*sy + fy, oz = roz*sz + fz;
    float dx = ux*sx, dy = uy*sy, dz = uz*sz;

    float dlen = sqrtf(dx*dx + dy*dy + dz*dz);
    float delta_scale = 1.0f/dlen;

    float ivx = 1.0f/((fabsf(dx) > 1e-9f) ? dx : 1e-9f);
    float ivy = 1.0f/((fabsf(dy) > 1e-9f) ? dy : 1e-9f);
    float ivz = 1.0f/((fabsf(dz) > 1e-9f) ? dz : 1e-9f);

    float t1x = (0.0f - ox)*ivx, t2x = (1.0f - ox)*ivx;
    float t1y = (0.0f - oy)*ivy, t2y = (1.0f - oy)*ivy;
    float t1z = (0.0f - oz)*ivz, t2z = (1.0f - oz)*ivz;

    float tlo = fmaxf(fmaxf(fminf(t1x,t2x), fminf(t1y,t2y)), fminf(t1z,t2z));
    float thi = fminf(fminf(fmaxf(t1x,t2x), fmaxf(t1y,t2y)), fmaxf(t1z,t2z));
    float tmin = fmaxf(tlo, 0.0f);

    float T = 1.0f, cr = 0.0f, cg = 0.0f, cb = 0.0f;

    if (thi > tmin) {
        float dt   = (thi - tmin) * (1.0f/(float)NSTEPS);
        float dtds = dt * delta_scale;

        const float C0 = 0.28209479177387814f;
        const float C1 = 0.4886025119029199f;
        float b0 = C0;
        float b1 = -C1*uy;
        float b2 =  C1*uz;
        float b3 = -C1*ux;
        float b4 =  1.0925484305920792f*ux*uy;
        float b5 = -1.0925484305920792f*uy*uz;
        float b6 =  0.31539156525252005f*(2.0f*uz*uz - ux*ux - uy*uy);
        float b7 = -1.0925484305920792f*ux*uz;
        float b8 =  0.5462742152960396f*(ux*ux - uy*uy);

        int cx = (c >> 2) & 1, cy = (c >> 1) & 1, cz = c & 1;
        // corner offset in halves: ((cx*128 + cy)*128 + cz) * 32
        int coff = ((cx << 14) + (cy << 7) + cz) << 5;

        float oxR = fmaf(ox, (float)RGRID, -0.5f);
        float oyR = fmaf(oy, (float)RGRID, -0.5f);
        float ozR = fmaf(oz, (float)RGRID, -0.5f);
        float dxR = dx*(float)RGRID, dyR = dy*(float)RGRID, dzR = dz*(float)RGRID;

        for (int s = 0; s < NSTEPS; ++s) {
            float t  = tmin + ((float)s + 0.5f)*dt;
            float px = fminf(fmaxf(fmaf(t, dxR, oxR), 0.0f), 126.9999f);
            float py = fminf(fmaxf(fmaf(t, dyR, oyR), 0.0f), 126.9999f);
            float pz = fminf(fmaxf(fmaf(t, dzR, ozR), 0.0f), 126.9999f);

            float gx = floorf(px), gy = floorf(py), gz = floorf(pz);
            int ix = (int)gx, iy = (int)gy, iz = (int)gz;
            float wxx = px - gx, wyy = py - gy, wzz = pz - gz;

            int base = (((ix << 7) + iy) << 12) + (iz << 5) + coff; // ((ix*128+iy)*128+iz)*32

            float wc = (cx ? wxx : 1.0f - wxx)
                     * (cy ? wyy : 1.0f - wyy)
                     * (cz ? wzz : 1.0f - wzz);

            // sigma pre-pass: channel 27
            float sg = gsum8(wc * __half2float(__ldg(g_grid16 + base + 27)), gmask);

            if (sg > 0.0f) {   // group-uniform
                const uint4* p = reinterpret_cast<const uint4*>(g_grid16 + base);
                uint4 q0 = __ldg(p+0);
                uint4 q1 = __ldg(p+1);
                uint4 q2 = __ldg(p+2);
                uint2 q3 = __ldg(reinterpret_cast<const uint2*>(p+3));

                float2 a0 = up(q0.x), a1 = up(q0.y), a2  = up(q0.z), a3  = up(q0.w);
                float2 a4 = up(q1.x), a5 = up(q1.y), a6  = up(q1.z), a7  = up(q1.w);
                float2 a8 = up(q2.x), a9 = up(q2.y), a10 = up(q2.z), a11 = up(q2.w);
                float2 a12 = up(q3.x), a13 = up(q3.y);

                float d0 = b0*a0.x + b1*a0.y + b2*a1.x + b3*a1.y
                         + b4*a2.x + b5*a2.y + b6*a3.x + b7*a3.y + b8*a4.x;
                float d1 = b0*a4.y + b1*a5.x + b2*a5.y + b3*a6.x
                         + b4*a6.y + b5*a7.x + b6*a7.y + b7*a8.x + b8*a8.y;
                float d2 = b0*a9.x + b1*a9.y + b2*a10.x + b3*a10.y
                         + b4*a11.x + b5*a11.y + b6*a12.x + b7*a12.y + b8*a13.x;

                float e0 = gsum8(wc * d0, gmask);
                float e1 = gsum8(wc * d1, gmask);
                float e2 = gsum8(wc * d2, gmask);

                float alpha = 1.0f - __expf(-sg*dtds);
                float s0 = 1.0f/(1.0f + __expf(-e0));
                float s1 = 1.0f/(1.0f + __expf(-e1));
                float s2 = 1.0f/(1.0f + __expf(-e2));

                float Ta = T*alpha;
                cr = fmaf(Ta, s0, cr);
                cg = fmaf(Ta, s1, cg);
                cb = fmaf(Ta, s2, cb);
                T  = T*(1.0f - alpha);
                if (T < 1e-4f) break;   // bounded 1e-4 abs error; group-uniform
            }
        }
    }

    if (c == 0) {
        out[3*ray+0] = fmaf(T, 1.0f, cr);
        out[3*ray+1] = fmaf(T, 1.0f, cg);
        out[3*ray+2] = fmaf(T, 1.0f, cb);
    }
}

extern "C" void kernel_launch(void* const* d_in, const int* in_sizes, int n_in,
                              void* d_out, int out_size) {
    const float* rays_o  = (const float*)d_in[0];
    const float* rays_d  = (const float*)d_in[1];
    const float* grid    = (const float*)d_in[2];
    const float* scaling = (const float*)d_in[3];
    const float* offset  = (const float*)d_in[4];
    float* out = (float*)d_out;

    // 1) repack grid to fp16, 64-B voxels
    convert_kernel<<<(NV + 255) / 256, 256>>>(grid);

    // 2) render
    int N = in_sizes[0] / 3;
    int threads_total = N * 8;
    int block = 256;
    int blocks = (threads_total + block - 1) / block;
    octree_render_kernel<<<blocks, block>>>(rays_o, rays_d, scaling, offset, out, N);
}

// round 5
// speedup vs baseline: 1.1339x; 1.0354x over previous
#include <cuda_runtime.h>
#include <cuda_fp16.h>

#define RGRID 128
#define NSTEPS 128
#define NCH 28
#define NV (RGRID*RGRID*RGRID)

// fp16 color grid: 32 halves (64 B) per voxel, 64-B aligned.
// [0..26] = SH coeffs, [27] = sigma copy (unused by render), [28..31] = pad.
__device__ __align__(16) __half g_grid16[(size_t)NV * 32];
// dense fp16 sigma grid: 4 MB, L2-resident
__device__ __align__(16) __half g_sigma[(size_t)NV];

__device__ __forceinline__ unsigned pk(float a, float b) {
    __half2 h = __floats2half2_rn(a, b);
    return *reinterpret_cast<unsigned*>(&h);
}
__device__ __forceinline__ float2 up(unsigned u) {
    __half2 h = *reinterpret_cast<__half2*>(&u);
    return __half22float2(h);
}

// One float4 (= 4 channels) per thread; 7 threads cover one voxel's 28 channels.
// Source reads are perfectly coalesced float4 streams.
__global__ void __launch_bounds__(256) convert_kernel(const float* __restrict__ grid) {
    int i = blockIdx.x * blockDim.x + threadIdx.x;
    if (i >= NV * 7) return;
    int v = i / 7;
    int j = i - v * 7;

    float4 f = __ldg(reinterpret_cast<const float4*>(grid) + i);

    uint2 q = make_uint2(pk(f.x, f.y), pk(f.z, f.w));
    *reinterpret_cast<uint2*>(g_grid16 + (size_t)v * 32 + j * 4) = q;

    if (j == 6) g_sigma[v] = __float2half(f.w);   // channel 27
}

__device__ __forceinline__ float gsum8(float v, unsigned m) {
    v += __shfl_xor_sync(m, v, 1);
    v += __shfl_xor_sync(m, v, 2);
    v += __shfl_xor_sync(m, v, 4);
    return v;
}

__global__ void __launch_bounds__(256, 4) octree_render_kernel(
    const float* __restrict__ rays_o,
    const float* __restrict__ rays_d,
    const float* __restrict__ scaling,
    const float* __restrict__ offset,
    float* __restrict__ out,
    int N)
{
    int tid  = blockIdx.x * blockDim.x + threadIdx.x;
    int ray  = tid >> 3;          // 8 lanes per ray
    int c    = tid & 7;           // corner id: bit2=dx, bit1=dy, bit0=dz
    if (ray >= N) return;

    int lane = threadIdx.x & 31;
    unsigned gmask = 0xFFu << (lane & 24);

    float rox = rays_o[3*ray+0], roy = rays_o[3*ray+1], roz = rays_o[3*ray+2];
    float rdx = rays_d[3*ray+0], rdy = rays_d[3*ray+1], rdz = rays_d[3*ray+2];

    float inv_n = rsqrtf(rdx*rdx + rdy*rdy + rdz*rdz);
    float ux = rdx*inv_n, uy = rdy*inv_n, uz = rdz*inv_n;

    float sx = scaling[0], sy = scaling[1], sz = scaling[2];
    float fx = offset[0],  fy = offset[1],  fz = offset[2];

    float ox = rox*sx + fx, oy = roy*sy + fy, oz = roz*sz + fz;
    float dx = ux*sx, dy = uy*sy, dz = uz*sz;

    float dlen = sqrtf(dx*dx + dy*dy + dz*dz);
    float delta_scale = 1.0f/dlen;

    float ivx = 1.0f/((fabsf(dx) > 1e-9f) ? dx : 1e-9f);
    float ivy = 1.0f/((fabsf(dy) > 1e-9f) ? dy : 1e-9f);
    float ivz = 1.0f/((fabsf(dz) > 1e-9f) ? dz : 1e-9f);

    float t1x = (0.0f - ox)*ivx, t2x = (1.0f - ox)*ivx;
    float t1y = (0.0f - oy)*ivy, t2y = (1.0f - oy)*ivy;
    float t1z = (0.0f - oz)*ivz, t2z = (1.0f - oz)*ivz;

    float tlo = fmaxf(fmaxf(fminf(t1x,t2x), fminf(t1y,t2y)), fminf(t1z,t2z));
    float thi = fminf(fminf(fmaxf(t1x,t2x), fmaxf(t1y,t2y)), fmaxf(t1z,t2z));
    float tmin = fmaxf(tlo, 0.0f);

    float T = 1.0f, cr = 0.0f, cg = 0.0f, cb = 0.0f;

    if (thi > tmin) {
        float dt   = (thi - tmin) * (1.0f/(float)NSTEPS);
        float dtds = dt * delta_scale;

        const float C0 = 0.28209479177387814f;
        const float C1 = 0.4886025119029199f;
        float b0 = C0;
        float b1 = -C1*uy;
        float b2 =  C1*uz;
        float b3 = -C1*ux;
        float b4 =  1.0925484305920792f*ux*uy;
        float b5 = -1.0925484305920792f*uy*uz;
        float b6 =  0.31539156525252005f*(2.0f*uz*uz - ux*ux - uy*uy);
        float b7 = -1.0925484305920792f*ux*uz;
        float b8 =  0.5462742152960396f*(ux*ux - uy*uy);

        int cx = (c >> 2) & 1, cy = (c >> 1) & 1, cz = c & 1;

        float oxR = fmaf(ox, (float)RGRID, -0.5f);
        float oyR = fmaf(oy, (float)RGRID, -0.5f);
        float ozR = fmaf(oz, (float)RGRID, -0.5f);
        float dxR = dx*(float)RGRID, dyR = dy*(float)RGRID, dzR = dz*(float)RGRID;

        for (int s = 0; s < NSTEPS; ++s) {
            float t  = tmin + ((float)s + 0.5f)*dt;
            float px = fminf(fmaxf(fmaf(t, dxR, oxR), 0.0f), 126.9999f);
            float py = fminf(fmaxf(fmaf(t, dyR, oyR), 0.0f), 126.9999f);
            float pz = fminf(fmaxf(fmaf(t, dzR, ozR), 0.0f), 126.9999f);

            float gx = floorf(px), gy = floorf(py), gz = floorf(pz);
            int ix = (int)gx, iy = (int)gy, iz = (int)gz;
            float wxx = px - gx, wyy = py - gy, wzz = pz - gz;

            // this corner's voxel index (components <= 127, no carries)
            int vi = ((ix + cx) << 14) + ((iy + cy) << 7) + (iz + cz);

            float wc = (cx ? wxx : 1.0f - wxx)
                     * (cy ? wyy : 1.0f - wyy)
                     * (cz ? wzz : 1.0f - wzz);

            // sigma pre-pass from the dense 4 MB sigma grid (L2-resident)
            float sg = gsum8(wc * __half2float(__ldg(g_sigma + vi)), gmask);

            if (sg > 0.0f) {   // group-uniform
                const uint4* p = reinterpret_cast<const uint4*>(g_grid16 + ((size_t)vi << 5));
                uint4 q0 = __ldg(p+0);
                uint4 q1 = __ldg(p+1);
                uint4 q2 = __ldg(p+2);
                uint2 q3 = __ldg(reinterpret_cast<const uint2*>(p+3));

                float2 a0 = up(q0.x), a1 = up(q0.y), a2  = up(q0.z), a3  = up(q0.w);
                float2 a4 = up(q1.x), a5 = up(q1.y), a6  = up(q1.z), a7  = up(q1.w);
                float2 a8 = up(q2.x), a9 = up(q2.y), a10 = up(q2.z), a11 = up(q2.w);
                float2 a12 = up(q3.x), a13 = up(q3.y);

                float d0 = b0*a0.x + b1*a0.y + b2*a1.x + b3*a1.y
                         + b4*a2.x + b5*a2.y + b6*a3.x + b7*a3.y + b8*a4.x;
                float d1 = b0*a4.y + b1*a5.x + b2*a5.y + b3*a6.x
                         + b4*a6.y + b5*a7.x + b6*a7.y + b7*a8.x + b8*a8.y;
                float d2 = b0*a9.x + b1*a9.y + b2*a10.x + b3*a10.y
                         + b4*a11.x + b5*a11.y + b6*a12.x + b7*a12.y + b8*a13.x;

                float e0 = gsum8(wc * d0, gmask);
                float e1 = gsum8(wc * d1, gmask);
                float e2 = gsum8(wc * d2, gmask);

                float alpha = 1.0f - __expf(-sg*dtds);
                float s0 = 1.0f/(1.0f + __expf(-e0));
                float s1 = 1.0f/(1.0f + __expf(-e1));
                float s2 = 1.0f/(1.0f + __expf(-e2));

                float Ta = T*alpha;
                cr = fmaf(Ta, s0, cr);
                cg = fmaf(Ta, s1, cg);
                cb = fmaf(Ta, s2, cb);
                T  = T*(1.0f - alpha);
                if (T < 1e-4f) break;   // bounded 1e-4 abs error; group-uniform
            }
        }
    }

    if (c == 0) {
        out[3*ray+0] = fmaf(T, 1.0f, cr);
        out[3*ray+1] = fmaf(T, 1.0f, cg);
        out[3*ray+2] = fmaf(T, 1.0f, cb);
    }
}

extern "C" void kernel_launch(void* const* d_in, const int* in_sizes, int n_in,
                              void* d_out, int out_size) {
    const float* rays_o  = (const float*)d_in[0];
    const float* rays_d  = (const float*)d_in[1];
    const float* grid    = (const float*)d_in[2];
    const float* scaling = (const float*)d_in[3];
    const float* offset  = (const float*)d_in[4];
    float* out = (float*)d_out;

    // 1) repack grid: fp16 color voxels + dense fp16 sigma array
    int convN = NV * 7;
    convert_kernel<<<(convN + 255) / 256, 256>>>(grid);

    // 2) render
    int N = in_sizes[0] / 3;
    int threads_total = N * 8;
    int block = 256;
    int blocks = (threads_total + block - 1) / block;
    octree_render_kernel<<<blocks, block>>>(rays_o, rays_d, scaling, offset, out, N);
}